// round 1
// baseline (speedup 1.0000x reference)
#include <cuda_runtime.h>
#include <cuda_bf16.h>

#define BATCH 8
#define CDIM  64
#define NPTS  4096
#define KNBR  16
#define KP1   17
#define COUT  64

// ---------------- scratch (no allocations allowed) ----------------
__device__ float g_sq [BATCH * NPTS];
__device__ int   g_idx[BATCH * NPTS * KNBR];
__device__ float g_A  [BATCH * NPTS * COUT];   // A[b][n][o] = W1 . x_n   (transposed layout, o contiguous)
__device__ float g_Cp [BATCH * NPTS * COUT];   // Cpre[b][n][o] = (W2-W1).x_n + b1+b2

typedef unsigned long long ull;

__device__ __forceinline__ ull pack2(float lo, float hi) {
    ull r; asm("mov.b64 %0, {%1,%2};" : "=l"(r) : "f"(lo), "f"(hi)); return r;
}
__device__ __forceinline__ void unpack2(ull v, float& lo, float& hi) {
    asm("mov.b64 {%0,%1}, %2;" : "=f"(lo), "=f"(hi) : "l"(v));
}
__device__ __forceinline__ void fma2(ull& acc, ull a, ull b) {
    asm("fma.rn.f32x2 %0, %1, %2, %0;" : "+l"(acc) : "l"(a), "l"(b));
}

// ---------------- kernel 1: squared norms ----------------
__global__ void sq_kernel(const float* __restrict__ x) {
    int b = blockIdx.y;
    int n = blockIdx.x * blockDim.x + threadIdx.x;
    const float* xp = x + (size_t)b * CDIM * NPTS + n;
    float s = 0.f;
#pragma unroll
    for (int c = 0; c < CDIM; ++c) {
        float v = xp[c * NPTS];
        s = fmaf(v, v, s);
    }
    g_sq[b * NPTS + n] = s;
}

// ---------------- kernel 2: fused distance-GEMM + top-17 KNN ----------------
// Block: 256 threads, TM=128 rows, candidate tiles of TC=64.
// Micro-tile per thread: 8 rows (4 f32x2 pairs) x 4 candidates.
#define TM 128
#define TC 64
#define KNN_SMEM ((CDIM*TM + CDIM*TC + TC + TM*(TC+1)) * 4)

__global__ __launch_bounds__(256, 2) void knn_kernel(const float* __restrict__ x) {
    extern __shared__ float sm[];
    float* rs   = sm;                       // [CDIM][TM]
    float* cs   = rs + CDIM * TM;           // [CDIM][TC]
    float* sqs  = cs + CDIM * TC;           // [TC]
    float* vbuf = sqs + TC;                 // [TM][TC+1]

    const int tid  = threadIdx.x;
    const int b    = blockIdx.y;
    const int row0 = blockIdx.x * TM;
    const float* xb = x + (size_t)b * CDIM * NPTS;

    // load row features rs[c][r]  (CDIM*TM = 8192 floats -> 8 float4/thread)
#pragma unroll
    for (int i = 0; i < 8; ++i) {
        int q  = tid + i * 256;
        int c  = q >> 5;          // 32 float4 per channel
        int mg = q & 31;
        *(float4*)(rs + c * TM + mg * 4) =
            *(const float4*)(xb + c * NPTS + row0 + mg * 4);
    }
    // load first candidate tile (CDIM*TC = 4096 floats -> 4 float4/thread)
#pragma unroll
    for (int i = 0; i < 4; ++i) {
        int q  = tid + i * 256;
        int c  = q >> 4;
        int mg = q & 15;
        *(float4*)(cs + c * TC + mg * 4) =
            *(const float4*)(xb + c * NPTS + mg * 4);
    }
    if (tid < 16)
        *(float4*)(sqs + tid * 4) = *(const float4*)(g_sq + b * NPTS + tid * 4);

    // per-row top-17 lists (only meaningful for tid < TM)
    float vk[KP1]; int ik[KP1];
#pragma unroll
    for (int s = 0; s < KP1; ++s) { vk[s] = 3.4e38f; ik[s] = 0x7fffffff; }

    __syncthreads();

    const int ty = tid >> 4;   // 0..15 -> rows ty*8 .. ty*8+7
    const int tx = tid & 15;   // 0..15 -> cands tx*4 .. tx*4+3
    const float* rp = rs + ty * 8;
    const float* cp = cs + tx * 4;
    const int NT = NPTS / TC;  // 64 tiles

    for (int t = 0; t < NT; ++t) {
        ull acc[4][4];
#pragma unroll
        for (int i = 0; i < 4; ++i)
#pragma unroll
            for (int j = 0; j < 4; ++j) acc[i][j] = 0ULL;

#pragma unroll 16
        for (int c = 0; c < CDIM; ++c) {
            float4 r0 = *(const float4*)(rp + c * TM);
            float4 r1 = *(const float4*)(rp + c * TM + 4);
            float4 cv = *(const float4*)(cp + c * TC);
            ull a0 = pack2(r0.x, r0.y);
            ull a1 = pack2(r0.z, r0.w);
            ull a2 = pack2(r1.x, r1.y);
            ull a3 = pack2(r1.z, r1.w);
            ull b0 = pack2(cv.x, cv.x);
            ull b1 = pack2(cv.y, cv.y);
            ull b2 = pack2(cv.z, cv.z);
            ull b3 = pack2(cv.w, cv.w);
            fma2(acc[0][0], a0, b0); fma2(acc[0][1], a0, b1);
            fma2(acc[0][2], a0, b2); fma2(acc[0][3], a0, b3);
            fma2(acc[1][0], a1, b0); fma2(acc[1][1], a1, b1);
            fma2(acc[1][2], a1, b2); fma2(acc[1][3], a1, b3);
            fma2(acc[2][0], a2, b0); fma2(acc[2][1], a2, b1);
            fma2(acc[2][2], a2, b2); fma2(acc[2][3], a2, b3);
            fma2(acc[3][0], a3, b0); fma2(acc[3][1], a3, b1);
            fma2(acc[3][2], a3, b2); fma2(acc[3][3], a3, b3);
        }

        // v = sq[m] - 2*dot  ->  vbuf[row][m]
#pragma unroll
        for (int i = 0; i < 4; ++i) {
#pragma unroll
            for (int j = 0; j < 4; ++j) {
                float d0, d1; unpack2(acc[i][j], d0, d1);
                int   m  = tx * 4 + j;
                float sv = sqs[m];
                int   r  = ty * 8 + i * 2;
                vbuf[r * (TC + 1) + m]       = fmaf(-2.f, d0, sv);
                vbuf[(r + 1) * (TC + 1) + m] = fmaf(-2.f, d1, sv);
            }
        }
        __syncthreads();   // vbuf ready; cs consumed

        if (tid < TM) {
            // merge 64 candidates into this row's top-17 (ties -> lower index)
            const int    mbase = t * TC;
            const float* vr    = vbuf + tid * (TC + 1);
#pragma unroll 4
            for (int j = 0; j < TC; ++j) {
                float v = vr[j];
                int   m = mbase + j;
                if (v < vk[KP1 - 1] || (v == vk[KP1 - 1] && m < ik[KP1 - 1])) {
#pragma unroll
                    for (int s = KP1 - 1; s >= 0; --s) {
                        bool up = (s > 0) &&
                                  ((v < vk[s - 1]) || (v == vk[s - 1] && m < ik[s - 1]));
                        if (up) { vk[s] = vk[s - 1]; ik[s] = ik[s - 1]; }
                        else    { vk[s] = v;        ik[s] = m;        break; }
                    }
                }
            }
        } else if (t + 1 < NT) {
            // other half of the block prefetches the next candidate tile
            int tb = (t + 1) * TC;
            int t2 = tid - 128;
#pragma unroll
            for (int i = 0; i < 8; ++i) {
                int q  = t2 + i * 128;
                int c  = q >> 4;
                int mg = q & 15;
                *(float4*)(cs + c * TC + mg * 4) =
                    *(const float4*)(xb + c * NPTS + tb + mg * 4);
            }
            if (t2 < 16)
                *(float4*)(sqs + t2 * 4) = *(const float4*)(g_sq + b * NPTS + tb + t2 * 4);
        }
        __syncthreads();
    }

    if (tid < TM) {
        int n = row0 + tid;
        int* op = g_idx + ((size_t)b * NPTS + n) * KNBR;
#pragma unroll
        for (int k = 0; k < KNBR; ++k) op[k] = ik[k + 1];  // drop self (rank 0)
    }
}

// ---------------- kernel 3: A = W1.x ; Cpre = (W2-W1).x + b1+b2 ----------------
__global__ void feat_kernel(const float* __restrict__ x,
                            const float* __restrict__ W1, const float* __restrict__ b1,
                            const float* __restrict__ W2, const float* __restrict__ b2) {
    __shared__ float xs [CDIM][64];   // [c][n]
    __shared__ float w1s[COUT][CDIM]; // [o][c] as-loaded
    __shared__ float wds[COUT][CDIM];
    __shared__ float bs [COUT];

    const int tid = threadIdx.x;
    const int b   = blockIdx.y;
    const int n0  = blockIdx.x * 64;
    const float* xb = x + (size_t)b * CDIM * NPTS;

#pragma unroll
    for (int i = 0; i < 4; ++i) {
        int q  = tid + i * 256;
        int c  = q >> 4;
        int mg = q & 15;
        *(float4*)(&xs[c][mg * 4]) = *(const float4*)(xb + c * NPTS + n0 + mg * 4);
    }
#pragma unroll
    for (int i = 0; i < 4; ++i) {
        int q  = tid + i * 256;
        int o  = q >> 4;
        int cg = (q & 15) * 4;
        float4 w1v = *(const float4*)(W1 + o * CDIM + cg);
        float4 w2v = *(const float4*)(W2 + o * CDIM + cg);
        *(float4*)(&w1s[o][cg]) = w1v;
        float4 wd = make_float4(w2v.x - w1v.x, w2v.y - w1v.y, w2v.z - w1v.z, w2v.w - w1v.w);
        *(float4*)(&wds[o][cg]) = wd;
    }
    if (tid < COUT) bs[tid] = b1[tid] + b2[tid];
    __syncthreads();

    const int tx = tid & 15;   // n group
    const int ty = tid >> 4;   // o group
    float aA[4][4] = {}, aC[4][4] = {};
#pragma unroll 16
    for (int c = 0; c < CDIM; ++c) {
        float4 xv = *(const float4*)(&xs[c][tx * 4]);
        float xr[4] = {xv.x, xv.y, xv.z, xv.w};
#pragma unroll
        for (int j = 0; j < 4; ++j) {
            float w1e = w1s[ty * 4 + j][c];
            float wde = wds[ty * 4 + j][c];
#pragma unroll
            for (int i = 0; i < 4; ++i) {
                aA[i][j] = fmaf(xr[i], w1e, aA[i][j]);
                aC[i][j] = fmaf(xr[i], wde, aC[i][j]);
            }
        }
    }
#pragma unroll
    for (int i = 0; i < 4; ++i) {
        int n = n0 + tx * 4 + i;
        float* ap = g_A  + ((size_t)b * NPTS + n) * COUT + ty * 4;
        float* cp = g_Cp + ((size_t)b * NPTS + n) * COUT + ty * 4;
        *(float4*)ap = make_float4(aA[i][0], aA[i][1], aA[i][2], aA[i][3]);
        *(float4*)cp = make_float4(aC[i][0] + bs[ty * 4 + 0],
                                   aC[i][1] + bs[ty * 4 + 1],
                                   aC[i][2] + bs[ty * 4 + 2],
                                   aC[i][3] + bs[ty * 4 + 3]);
    }
}

// ---------------- kernel 4: gather-max + relu, write [B][Cout][1][N] ----------------
__global__ void gather_kernel(float* __restrict__ out) {
    const int tid = threadIdx.x;
    const int b   = blockIdx.y;
    const int n   = blockIdx.x * 64 + (tid & 63);
    const int g   = tid >> 6;                     // channel group: g*16 .. g*16+15
    const int* ip = g_idx + ((size_t)b * NPTS + n) * KNBR;

    float mx[16];
#pragma unroll
    for (int i = 0; i < 16; ++i) mx[i] = -3.4e38f;

#pragma unroll
    for (int k = 0; k < KNBR; ++k) {
        int j = ip[k];
        const float4* ap = (const float4*)(g_A + ((size_t)b * NPTS + j) * COUT + g * 16);
#pragma unroll
        for (int q = 0; q < 4; ++q) {
            float4 v = ap[q];
            mx[q * 4 + 0] = fmaxf(mx[q * 4 + 0], v.x);
            mx[q * 4 + 1] = fmaxf(mx[q * 4 + 1], v.y);
            mx[q * 4 + 2] = fmaxf(mx[q * 4 + 2], v.z);
            mx[q * 4 + 3] = fmaxf(mx[q * 4 + 3], v.w);
        }
    }
    const float4* cp = (const float4*)(g_Cp + ((size_t)b * NPTS + n) * COUT + g * 16);
    float* op = out + ((size_t)b * COUT + g * 16) * NPTS + n;
#pragma unroll
    for (int q = 0; q < 4; ++q) {
        float4 c = cp[q];
        op[(q * 4 + 0) * NPTS] = fmaxf(c.x + mx[q * 4 + 0], 0.f);
        op[(q * 4 + 1) * NPTS] = fmaxf(c.y + mx[q * 4 + 1], 0.f);
        op[(q * 4 + 2) * NPTS] = fmaxf(c.z + mx[q * 4 + 2], 0.f);
        op[(q * 4 + 3) * NPTS] = fmaxf(c.w + mx[q * 4 + 3], 0.f);
    }
}

// ---------------- launch ----------------
extern "C" void kernel_launch(void* const* d_in, const int* in_sizes, int n_in,
                              void* d_out, int out_size) {
    const float *x = nullptr, *W1 = nullptr, *b1 = nullptr, *W2 = nullptr, *b2 = nullptr;
    for (int i = 0; i < n_in; ++i) {
        int s = in_sizes[i];
        const float* p = (const float*)d_in[i];
        if      (s == BATCH * CDIM * NPTS) x = p;
        else if (s == COUT * CDIM)        { if (!W1) W1 = p; else W2 = p; }
        else if (s == COUT)               { if (!b1) b1 = p; else b2 = p; }
    }
    float* out = (float*)d_out;

    static bool attr_done = false;
    cudaFuncSetAttribute(knn_kernel, cudaFuncAttributeMaxDynamicSharedMemorySize, KNN_SMEM);
    (void)attr_done; (void)out_size;

    sq_kernel    <<<dim3(NPTS / 256, BATCH), 256>>>(x);
    knn_kernel   <<<dim3(NPTS / TM, BATCH), 256, KNN_SMEM>>>(x);
    feat_kernel  <<<dim3(NPTS / 64, BATCH), 256>>>(x, W1, b1, W2, b2);
    gather_kernel<<<dim3(NPTS / 64, BATCH), 256>>>(out);
}

// round 2
// speedup vs baseline: 6.6663x; 6.6663x over previous
#include <cuda_runtime.h>
#include <cuda_bf16.h>

#define BATCH 8
#define CDIM  64
#define NPTS  4096
#define KNBR  16
#define COUT  64

// ---------------- scratch (no allocations allowed) ----------------
__device__ float g_sq [BATCH * NPTS];
__device__ int   g_idx[BATCH * NPTS * KNBR];
__device__ float g_A  [BATCH * NPTS * COUT];   // A[b][n][o] = W1 . x_n
__device__ float g_Cp [BATCH * NPTS * COUT];   // Cpre[b][n][o] = (W2-W1).x_n + b1+b2

typedef unsigned long long ull;

__device__ __forceinline__ ull pack2(float lo, float hi) {
    ull r; asm("mov.b64 %0, {%1,%2};" : "=l"(r) : "f"(lo), "f"(hi)); return r;
}
__device__ __forceinline__ void unpack2(ull v, float& lo, float& hi) {
    asm("mov.b64 {%0,%1}, %2;" : "=f"(lo), "=f"(hi) : "l"(v));
}
__device__ __forceinline__ void fma2(ull& acc, ull a, ull b) {
    asm("fma.rn.f32x2 %0, %1, %2, %0;" : "+l"(acc) : "l"(a), "l"(b));
}
// monotone float->uint mapping (order-preserving, incl. negatives)
__device__ __forceinline__ unsigned fsort(float v) {
    unsigned u = __float_as_uint(v);
    return u ^ (0x80000000u | (unsigned)((int)u >> 31));
}
__device__ __forceinline__ float funsort(unsigned s) {
    unsigned u = (s & 0x80000000u) ? (s ^ 0x80000000u) : ~s;
    return __uint_as_float(u);
}

// ---------------- kernel 1: squared norms ----------------
__global__ void sq_kernel(const float* __restrict__ x) {
    int b = blockIdx.y;
    int n = blockIdx.x * blockDim.x + threadIdx.x;
    const float* xp = x + (size_t)b * CDIM * NPTS + n;
    float s = 0.f;
#pragma unroll
    for (int c = 0; c < CDIM; ++c) {
        float v = xp[c * NPTS];
        s = fmaf(v, v, s);
    }
    g_sq[b * NPTS + n] = s;
}

// ---------------- kernel 2: fused distance-GEMM + threshold/flush KNN ----------------
#define TM 128
#define TC 64
#define PSTRIDE 65   // padded pending stride (bank-conflict free)

// smem layout (bytes)
#define SM_RS   0                              // float[64*128]  32768
#define SM_CS   (SM_RS + CDIM*TM*4)            // float[64*64]   16384
#define SM_SQS  (SM_CS + CDIM*TC*4)            // float[64]        256
#define SM_THR  (SM_SQS + TC*4)                // float[128]       512
#define SM_CNT  (SM_THR + TM*4)                // int[128]         512
#define SM_PV   (SM_CNT + TM*4)                // float[128*65]  33280
#define SM_PI   (SM_PV + TM*PSTRIDE*4)         // ushort[128*65] 16640
#define KNN_SMEM (SM_PI + TM*PSTRIDE*2)

__global__ __launch_bounds__(256, 2) void knn_kernel(const float* __restrict__ x) {
    extern __shared__ char smraw[];
    float*          rs  = (float*)(smraw + SM_RS);
    float*          cs  = (float*)(smraw + SM_CS);
    float*          sqs = (float*)(smraw + SM_SQS);
    float*          thr = (float*)(smraw + SM_THR);
    int*            cnt = (int*)  (smraw + SM_CNT);
    float*          pv  = (float*)(smraw + SM_PV);
    unsigned short* pi  = (unsigned short*)(smraw + SM_PI);

    const int tid  = threadIdx.x;
    const int b    = blockIdx.y;
    const int row0 = blockIdx.x * TM;
    const float* xb = x + (size_t)b * CDIM * NPTS;

    // ---- initial loads ----
#pragma unroll
    for (int i = 0; i < 8; ++i) {               // rs: 8192 floats
        int q = tid + i * 256, c = q >> 5, mg = q & 31;
        *(float4*)(rs + c * TM + mg * 4) = *(const float4*)(xb + c * NPTS + row0 + mg * 4);
    }
#pragma unroll
    for (int i = 0; i < 4; ++i) {               // cs tile 0: 4096 floats
        int q = tid + i * 256, c = q >> 4, mg = q & 15;
        *(float4*)(cs + c * TC + mg * 4) = *(const float4*)(xb + c * NPTS + mg * 4);
    }
    if (tid < 16)
        *(float4*)(sqs + tid * 4) = *(const float4*)(g_sq + b * NPTS + tid * 4);
    if (tid < TM) { thr[tid] = 3.4e38f; cnt[tid] = 0; }

    // per-row top-16 (unsorted, 64-bit sortable keys), rows owned by tid<128
    ull list[KNBR]; ull worst = ~0ULL; int wpos = 0;
#pragma unroll
    for (int s = 0; s < KNBR; ++s) list[s] = ~0ULL;

    __syncthreads();

    const int ty = tid >> 4;     // row group: rows ty*8 .. ty*8+7
    const int tx = tid & 15;     // cand group: cands tx*4 .. tx*4+3
    const float* rp = rs + ty * 8;
    const float* cp = cs + tx * 4;
    const int NT = NPTS / TC;

    for (int t = 0; t < NT; ++t) {
        // ================= GEMM: 8 rows x 4 cands, f32x2 =================
        ull acc[4][4];
#pragma unroll
        for (int i = 0; i < 4; ++i)
#pragma unroll
            for (int j = 0; j < 4; ++j) acc[i][j] = 0ULL;

#pragma unroll 16
        for (int c = 0; c < CDIM; ++c) {
            float4 r0 = *(const float4*)(rp + c * TM);
            float4 r1 = *(const float4*)(rp + c * TM + 4);
            float4 cv = *(const float4*)(cp + c * TC);
            ull a0 = pack2(r0.x, r0.y);
            ull a1 = pack2(r0.z, r0.w);
            ull a2 = pack2(r1.x, r1.y);
            ull a3 = pack2(r1.z, r1.w);
            ull b0 = pack2(cv.x, cv.x);
            ull b1 = pack2(cv.y, cv.y);
            ull b2 = pack2(cv.z, cv.z);
            ull b3 = pack2(cv.w, cv.w);
            fma2(acc[0][0], a0, b0); fma2(acc[0][1], a0, b1);
            fma2(acc[0][2], a0, b2); fma2(acc[0][3], a0, b3);
            fma2(acc[1][0], a1, b0); fma2(acc[1][1], a1, b1);
            fma2(acc[1][2], a1, b2); fma2(acc[1][3], a1, b3);
            fma2(acc[2][0], a2, b0); fma2(acc[2][1], a2, b1);
            fma2(acc[2][2], a2, b2); fma2(acc[2][3], a2, b3);
            fma2(acc[3][0], a3, b0); fma2(acc[3][1], a3, b1);
            fma2(acc[3][2], a3, b2); fma2(acc[3][3], a3, b3);
        }

        // ================= epilogue: threshold test + append =================
        {
            const int tb = t * TC;
            float tr[8];
#pragma unroll
            for (int i = 0; i < 8; ++i) tr[i] = thr[ty * 8 + i];
#pragma unroll
            for (int i = 0; i < 4; ++i) {
#pragma unroll
                for (int j = 0; j < 4; ++j) {
                    float d0, d1; unpack2(acc[i][j], d0, d1);
                    int   ml = tx * 4 + j;
                    float sv = sqs[ml];
                    int   mg = tb + ml;
                    int   ra = ty * 8 + i * 2;
                    float v0 = fmaf(-2.f, d0, sv);
                    float v1 = fmaf(-2.f, d1, sv);
                    if (v0 <= tr[i * 2]) {
                        int pos = atomicAdd(&cnt[ra], 1);
                        pv[ra * PSTRIDE + pos] = v0;
                        pi[ra * PSTRIDE + pos] =
                            (mg == row0 + ra) ? (unsigned short)0xFFFFu : (unsigned short)mg;
                    }
                    if (v1 <= tr[i * 2 + 1]) {
                        int pos = atomicAdd(&cnt[ra + 1], 1);
                        pv[(ra + 1) * PSTRIDE + pos] = v1;
                        pi[(ra + 1) * PSTRIDE + pos] =
                            (mg == row0 + ra + 1) ? (unsigned short)0xFFFFu : (unsigned short)mg;
                    }
                }
            }
        }
        __syncthreads();   // appends visible; cs/sqs consumed

        if (tid < TM) {
            // ============ flush: stream pendings through top-16 ============
            unsigned myc  = (unsigned)cnt[tid];
            unsigned cmax = __reduce_max_sync(0xffffffffu, myc);
            for (unsigned j = 0; j < cmax; ++j) {
                ull key = ~0ULL;
                if (j < myc) {
                    float    v  = pv[tid * PSTRIDE + j];
                    unsigned ix = pi[tid * PSTRIDE + j];
                    key = ((ull)fsort(v) << 32) | ix;
                    if (ix == 0xFFFFu) key = ~0ULL;   // self
                }
                bool take = key < worst;
                if (__any_sync(0xffffffffu, take)) {
#pragma unroll
                    for (int s = 0; s < KNBR; ++s)
                        if (take && s == wpos) list[s] = key;
                    ull w = list[0]; int p = 0;
#pragma unroll
                    for (int s = 1; s < KNBR; ++s)
                        if (list[s] > w) { w = list[s]; p = s; }
                    worst = w; wpos = p;
                }
            }
            float nthr = (worst == ~0ULL) ? 3.4e38f : funsort((unsigned)(worst >> 32));
            thr[tid] = nthr;
            cnt[tid] = 0;
        } else if (t + 1 < NT) {
            // ============ prefetch next candidate tile ============
            const int tb2 = (t + 1) * TC;
            const int t2  = tid - 128;
#pragma unroll
            for (int i = 0; i < 8; ++i) {
                int q = t2 + i * 128, c = q >> 4, mg = q & 15;
                *(float4*)(cs + c * TC + mg * 4) =
                    *(const float4*)(xb + c * NPTS + tb2 + mg * 4);
            }
            if (t2 < 16)
                *(float4*)(sqs + t2 * 4) = *(const float4*)(g_sq + b * NPTS + tb2 + t2 * 4);
        }
        __syncthreads();
    }

    if (tid < TM) {
        int* op = g_idx + ((size_t)b * NPTS + row0 + tid) * KNBR;
#pragma unroll
        for (int k = 0; k < KNBR; ++k) op[k] = (int)(list[k] & 0xFFFFu);
    }
}

// ---------------- kernel 3: A = W1.x ; Cpre = (W2-W1).x + b1+b2 ----------------
__global__ void feat_kernel(const float* __restrict__ x,
                            const float* __restrict__ W1, const float* __restrict__ b1,
                            const float* __restrict__ W2, const float* __restrict__ b2) {
    __shared__ float xs [CDIM][64];
    __shared__ float w1s[COUT][CDIM];
    __shared__ float wds[COUT][CDIM];
    __shared__ float bs [COUT];

    const int tid = threadIdx.x;
    const int b   = blockIdx.y;
    const int n0  = blockIdx.x * 64;
    const float* xb = x + (size_t)b * CDIM * NPTS;

#pragma unroll
    for (int i = 0; i < 4; ++i) {
        int q = tid + i * 256, c = q >> 4, mg = q & 15;
        *(float4*)(&xs[c][mg * 4]) = *(const float4*)(xb + c * NPTS + n0 + mg * 4);
    }
#pragma unroll
    for (int i = 0; i < 4; ++i) {
        int q = tid + i * 256, o = q >> 4, cg = (q & 15) * 4;
        float4 w1v = *(const float4*)(W1 + o * CDIM + cg);
        float4 w2v = *(const float4*)(W2 + o * CDIM + cg);
        *(float4*)(&w1s[o][cg]) = w1v;
        *(float4*)(&wds[o][cg]) = make_float4(w2v.x - w1v.x, w2v.y - w1v.y,
                                              w2v.z - w1v.z, w2v.w - w1v.w);
    }
    if (tid < COUT) bs[tid] = b1[tid] + b2[tid];
    __syncthreads();

    const int tx = tid & 15;
    const int ty = tid >> 4;
    float aA[4][4] = {}, aC[4][4] = {};
#pragma unroll 16
    for (int c = 0; c < CDIM; ++c) {
        float4 xv = *(const float4*)(&xs[c][tx * 4]);
        float xr[4] = {xv.x, xv.y, xv.z, xv.w};
#pragma unroll
        for (int j = 0; j < 4; ++j) {
            float w1e = w1s[ty * 4 + j][c];
            float wde = wds[ty * 4 + j][c];
#pragma unroll
            for (int i = 0; i < 4; ++i) {
                aA[i][j] = fmaf(xr[i], w1e, aA[i][j]);
                aC[i][j] = fmaf(xr[i], wde, aC[i][j]);
            }
        }
    }
#pragma unroll
    for (int i = 0; i < 4; ++i) {
        int n = n0 + tx * 4 + i;
        float* ap = g_A  + ((size_t)b * NPTS + n) * COUT + ty * 4;
        float* cp = g_Cp + ((size_t)b * NPTS + n) * COUT + ty * 4;
        *(float4*)ap = make_float4(aA[i][0], aA[i][1], aA[i][2], aA[i][3]);
        *(float4*)cp = make_float4(aC[i][0] + bs[ty * 4 + 0],
                                   aC[i][1] + bs[ty * 4 + 1],
                                   aC[i][2] + bs[ty * 4 + 2],
                                   aC[i][3] + bs[ty * 4 + 3]);
    }
}

// ---------------- kernel 4: gather-max + relu, write [B][Cout][1][N] ----------------
__global__ void gather_kernel(float* __restrict__ out) {
    const int tid = threadIdx.x;
    const int b   = blockIdx.y;
    const int n   = blockIdx.x * 64 + (tid & 63);
    const int g   = tid >> 6;
    const int* ip = g_idx + ((size_t)b * NPTS + n) * KNBR;

    float mx[16];
#pragma unroll
    for (int i = 0; i < 16; ++i) mx[i] = -3.4e38f;

#pragma unroll
    for (int k = 0; k < KNBR; ++k) {
        int j = ip[k];
        const float4* ap = (const float4*)(g_A + ((size_t)b * NPTS + j) * COUT + g * 16);
#pragma unroll
        for (int q = 0; q < 4; ++q) {
            float4 v = ap[q];
            mx[q * 4 + 0] = fmaxf(mx[q * 4 + 0], v.x);
            mx[q * 4 + 1] = fmaxf(mx[q * 4 + 1], v.y);
            mx[q * 4 + 2] = fmaxf(mx[q * 4 + 2], v.z);
            mx[q * 4 + 3] = fmaxf(mx[q * 4 + 3], v.w);
        }
    }
    const float4* cp = (const float4*)(g_Cp + ((size_t)b * NPTS + n) * COUT + g * 16);
    float* op = out + ((size_t)b * COUT + g * 16) * NPTS + n;
#pragma unroll
    for (int q = 0; q < 4; ++q) {
        float4 c = cp[q];
        op[(q * 4 + 0) * NPTS] = fmaxf(c.x + mx[q * 4 + 0], 0.f);
        op[(q * 4 + 1) * NPTS] = fmaxf(c.y + mx[q * 4 + 1], 0.f);
        op[(q * 4 + 2) * NPTS] = fmaxf(c.z + mx[q * 4 + 2], 0.f);
        op[(q * 4 + 3) * NPTS] = fmaxf(c.w + mx[q * 4 + 3], 0.f);
    }
}

// ---------------- launch ----------------
extern "C" void kernel_launch(void* const* d_in, const int* in_sizes, int n_in,
                              void* d_out, int out_size) {
    const float *x = nullptr, *W1 = nullptr, *b1 = nullptr, *W2 = nullptr, *b2 = nullptr;
    for (int i = 0; i < n_in; ++i) {
        int s = in_sizes[i];
        const float* p = (const float*)d_in[i];
        if      (s == BATCH * CDIM * NPTS) x = p;
        else if (s == COUT * CDIM)        { if (!W1) W1 = p; else W2 = p; }
        else if (s == COUT)               { if (!b1) b1 = p; else b2 = p; }
    }
    float* out = (float*)d_out;
    (void)out_size;

    cudaFuncSetAttribute(knn_kernel, cudaFuncAttributeMaxDynamicSharedMemorySize, KNN_SMEM);

    sq_kernel    <<<dim3(NPTS / 256, BATCH), 256>>>(x);
    knn_kernel   <<<dim3(NPTS / TM, BATCH), 256, KNN_SMEM>>>(x);
    feat_kernel  <<<dim3(NPTS / 64, BATCH), 256>>>(x, W1, b1, W2, b2);
    gather_kernel<<<dim3(NPTS / 64, BATCH), 256>>>(out);
}